// round 11
// baseline (speedup 1.0000x reference)
#include <cuda_runtime.h>

constexpr int B_ = 8192;
constexpr int K_ = 32;
constexpr int D_ = 129;
constexpr int V_ = 2048;
constexpr int KTOP = 10;
constexpr float WEIGHT_ = 0.15f;
constexpr int WARPS_PER_BLK = 4;
constexpr int ROWS_PER_WARP = 2;
constexpr int BLOCKS = B_ / (WARPS_PER_BLK * ROWS_PER_WARP);   // 1024

__device__ float g_part[BLOCKS];
__device__ int   g_count = 0;

__device__ __forceinline__ float warp_sum(float v) {
#pragma unroll
    for (int o = 16; o; o >>= 1) v += __shfl_xor_sync(0xffffffffu, v, o);
    return v;
}
__device__ __forceinline__ float warp_max(float v) {
#pragma unroll
    for (int o = 16; o; o >>= 1) v = fmaxf(v, __shfl_xor_sync(0xffffffffu, v, o));
    return v;
}
__device__ __forceinline__ float acoshd(float x) {
    x = fmaxf(x, 1.0f + 1e-7f);
    return __logf(x + sqrtf(fmaf(x, x, -1.0f)));
}
__device__ __forceinline__ float inv_log2(float n) {
    return __fdividef(1.0f, __log2f(n));
}
__device__ __forceinline__ float pair_term(float ri, float ci, float di,
                                           float rj, float cj, float dj,
                                           float inv_idcg) {
    float drel  = ri - rj;
    float delta = fabsf(drel * (ci - cj)) * inv_idcg;
    float dd    = dj - di;
    float s     = (drel > 0.0f) ? 1.0f : -1.0f;
    float x     = s * dd;
    float sig   = __fdividef(1.0f, 1.0f + __expf(-x));
    return s * delta * sig * (-dd);
}

// 8-item tile: fold 32->8 lanes, transpose-reduce; returns total of item
// (lane & 7), replicated across all four octets. (verified exact in R5)
__device__ __forceinline__ float tile_reduce8(float q[8], int lane) {
#pragma unroll
    for (int k = 0; k < 8; k++) {
        q[k] += __shfl_xor_sync(0xffffffffu, q[k], 16);
        q[k] += __shfl_xor_sync(0xffffffffu, q[k], 8);
    }
    const int ll = lane & 7;
#pragma unroll
    for (int m = 4; m >= 1; m >>= 1) {
        const bool up = (ll & m) != 0;
#pragma unroll
        for (int t = 0; t < m; t++) {
            float send = up ? q[t] : q[t + m];
            float recv = __shfl_xor_sync(0xffffffffu, send, m);
            q[t] = (up ? q[t + m] : q[t]) + recv;
        }
    }
    return q[0];
}

// full per-row epilogue from distances+tree values; returns warp-summed loss_b
__device__ __forceinline__ float row_epilogue(float dsum, float s32,
                                              float tme, float t32, int lane) {
    const float dme = acoshd(dsum);
    const float d32 = acoshd(s32);

    const float maxt   = fmaxf(warp_max(tme), t32);
    const float inv_mt = __fdividef(1.0f, maxt + 1e-6f);
    const float relme  = (maxt - tme + 1e-6f) * inv_mt;
    const float rel32  = (maxt - t32 + 1e-6f) * inv_mt;

    int rank = 1, rr = 0;
#pragma unroll
    for (int o = 1; o < 32; o++) {
        const int j = (lane + o) & 31;
        const float dj = __shfl_sync(0xffffffffu, dme,   j);
        const float rj = __shfl_sync(0xffffffffu, relme, j);
        rank += (dj < dme)   || (dj == dme   && j < lane);
        rr   += (rj > relme) || (rj == relme && j < lane);
    }
    rank += (d32 < dme);
    rr   += (rel32 > relme);

    const int rank32 = 1 + (int)__reduce_add_sync(0xffffffffu, (unsigned)(dme <= d32));
    const int rr32   =     (int)__reduce_add_sync(0xffffffffu, (unsigned)(relme >= rel32));

    const float cme = (rank   <= KTOP) ? inv_log2((float)(rank   + 1)) : 0.0f;
    const float c32 = (rank32 <= KTOP) ? inv_log2((float)(rank32 + 1)) : 0.0f;

    float ic = (rr < KTOP) ? relme * inv_log2((float)(rr + 2)) : 0.0f;
    if (lane == 0 && rr32 < KTOP) ic += rel32 * inv_log2((float)(rr32 + 2));
    const float idcg = warp_sum(ic);
    const float inv_idcg = (idcg > 0.0f) ? __fdividef(1.0f, idcg) : 0.0f;

    float acc = 0.0f;
#pragma unroll
    for (int o = 1; o <= 16; o++) {
        const int j = (lane + o) & 31;
        const float rj = __shfl_sync(0xffffffffu, relme, j);
        const float cj = __shfl_sync(0xffffffffu, cme,   j);
        const float dj = __shfl_sync(0xffffffffu, dme,   j);
        const float t  = pair_term(relme, cme, dme, rj, cj, dj, inv_idcg);
        acc += (o == 16) ? 0.5f * t : t;
    }
    acc += pair_term(relme, cme, dme, rel32, c32, d32, inv_idcg);
    return warp_sum(acc);
}

__global__ void __launch_bounds__(128, 8) lr_fused(
    const float* __restrict__ anchor,
    const float* __restrict__ positive,
    const float* __restrict__ negative,
    const float* __restrict__ tree,
    const int*   __restrict__ aidx,
    const int*   __restrict__ pidx,
    const int*   __restrict__ nidx,
    float*       __restrict__ out)
{
    __shared__ float s_warp[WARPS_PER_BLK];
    __shared__ float s_fin[128];
    __shared__ bool  s_last;

    const int w    = threadIdx.x >> 5;
    const int lane = threadIdx.x & 31;
    const int oct  = lane >> 3;
    const int bA   = (blockIdx.x * WARPS_PER_BLK + w) * ROWS_PER_WARP;
    const int bB   = bA + 1;

    const float* __restrict__ pbA = positive + (size_t)bA * D_;
    const float* __restrict__ nbA = negative + (size_t)bA * K_ * D_;
    const float* __restrict__ pbB = positive + (size_t)bB * D_;
    const float* __restrict__ nbB = negative + (size_t)bB * K_ * D_;

    // dependent gather chains for both rows: issue first
    const int aiA = __ldg(aidx + bA);
    const int aiB = __ldg(aidx + bB);
    const int colmeA = (lane == 0) ? __ldg(pidx + bA) : __ldg(nidx + bA * K_ + lane - 1);
    const int colmeB = (lane == 0) ? __ldg(pidx + bB) : __ldg(nidx + bB * K_ + lane - 1);
    const int col32A = __ldg(nidx + bA * K_ + 31);
    const int col32B = __ldg(nidx + bB * K_ + 31);

    // anchors (sign-flipped for c>=1: sum(ah_c*v_c) = -lorentz_inner)
    const float* arA = anchor + (size_t)bA * D_;
    const float* arB = anchor + (size_t)bB * D_;
    float ahA[4], ahB[4];
    ahA[0] = (lane == 0) ? arA[0] : -arA[lane];
    ahB[0] = (lane == 0) ? arB[0] : -arB[lane];
#pragma unroll
    for (int k = 1; k < 4; k++) { ahA[k] = -arA[lane + 32 * k]; ahB[k] = -arB[lane + 32 * k]; }
    const float a128A = -arA[128];
    const float a128B = -arB[128];

    float qa[8], qb[8], dsumA, dsumB;

#define LOAD8(buf, pb_, nb_, ah_, g)                                              \
    _Pragma("unroll")                                                             \
    for (int k = 0; k < 8; k++) {                                                 \
        const float* v = ((g) == 0 && k == 0) ? (pb_)                             \
                         : ((nb_) + (8 * (g) + k - 1) * D_);                      \
        buf[k] = fmaf(ah_[0], __ldcs(v + lane), fmaf(ah_[1], __ldcs(v + lane + 32),\
                 fmaf(ah_[2], __ldcs(v + lane + 64), ah_[3] * __ldcs(v + lane + 96))));\
    }

    // ===== interleaved pipeline: A/B ping-pong, always >=1 burst in flight =====
    LOAD8(qa, pbA, nbA, ahA, 0)
    LOAD8(qb, pbB, nbB, ahB, 0)
    // tree gathers under the first bursts
    const float* trA = tree + (size_t)aiA * V_;
    const float* trB = tree + (size_t)aiB * V_;
    const float tmeA = __ldg(trA + colmeA);
    const float t32A = __ldg(trA + col32A);
    const float tmeB = __ldg(trB + colmeB);
    const float t32B = __ldg(trB + col32B);

    { float v = tile_reduce8(qa, lane); if (oct == 0) dsumA = v; }
    LOAD8(qa, pbA, nbA, ahA, 1)
    { float v = tile_reduce8(qb, lane); if (oct == 0) dsumB = v; }
    LOAD8(qb, pbB, nbB, ahB, 1)
    { float v = tile_reduce8(qa, lane); if (oct == 1) dsumA = v; }
    LOAD8(qa, pbA, nbA, ahA, 2)
    { float v = tile_reduce8(qb, lane); if (oct == 1) dsumB = v; }
    LOAD8(qb, pbB, nbB, ahB, 2)
    { float v = tile_reduce8(qa, lane); if (oct == 2) dsumA = v; }
    LOAD8(qa, pbA, nbA, ahA, 3)
    { float v = tile_reduce8(qb, lane); if (oct == 2) dsumB = v; }
    LOAD8(qb, pbB, nbB, ahB, 3)
#undef LOAD8

    // item-32 partials + e128 tails, issued under the final bursts
    float p32A, p32B;
    {
        const float* v = nbA + 31 * D_;
        p32A = fmaf(ahA[0], __ldcs(v + lane), fmaf(ahA[1], __ldcs(v + lane + 32),
               fmaf(ahA[2], __ldcs(v + lane + 64), ahA[3] * __ldcs(v + lane + 96))));
    }
    {
        const float* v = nbB + 31 * D_;
        p32B = fmaf(ahB[0], __ldcs(v + lane), fmaf(ahB[1], __ldcs(v + lane + 32),
               fmaf(ahB[2], __ldcs(v + lane + 64), ahB[3] * __ldcs(v + lane + 96))));
    }
    const float e128meA = __ldcs(((lane == 0) ? pbA : (nbA + (lane - 1) * D_)) + 128);
    const float e128meB = __ldcs(((lane == 0) ? pbB : (nbB + (lane - 1) * D_)) + 128);
    const float e12832A = __ldcs(nbA + 31 * D_ + 128);
    const float e12832B = __ldcs(nbB + 31 * D_ + 128);

    // finish row A; epilogue A runs while row B's last burst + tails drain
    { float v = tile_reduce8(qa, lane); if (oct == 3) dsumA = v; }
    dsumA += a128A * e128meA;
    const float s32A = warp_sum(p32A) + a128A * e12832A;
    const float accA = row_epilogue(dsumA, s32A, tmeA, t32A, lane);

    { float v = tile_reduce8(qb, lane); if (oct == 3) dsumB = v; }
    dsumB += a128B * e128meB;
    const float s32B = warp_sum(p32B) + a128B * e12832B;
    const float accB = row_epilogue(dsumB, s32B, tmeB, t32B, lane);

    if (lane == 0) s_warp[w] = accA + accB;
    __syncthreads();

    if (threadIdx.x == 0) {
        float bsum = 0.0f;
#pragma unroll
        for (int i = 0; i < WARPS_PER_BLK; i++) bsum += s_warp[i];
        g_part[blockIdx.x] = bsum;
        __threadfence();
        const int prev = atomicAdd(&g_count, 1);
        s_last = (prev == BLOCKS - 1);
    }
    __syncthreads();

    if (s_last) {
        __threadfence();
        float v = 0.0f;
        for (int i = threadIdx.x; i < BLOCKS; i += 128) v += g_part[i];
        s_fin[threadIdx.x] = v;
        __syncthreads();
#pragma unroll
        for (int o = 64; o; o >>= 1) {
            if (threadIdx.x < o) s_fin[threadIdx.x] += s_fin[threadIdx.x + o];
            __syncthreads();
        }
        if (threadIdx.x == 0) {
            out[0] = WEIGHT_ * s_fin[0] / (float)B_;
            g_count = 0;
        }
    }
}

extern "C" void kernel_launch(void* const* d_in, const int* in_sizes, int n_in,
                              void* d_out, int out_size)
{
    const float* anchor   = (const float*)d_in[0];
    const float* positive = (const float*)d_in[1];
    const float* negative = (const float*)d_in[2];
    const float* tree     = (const float*)d_in[3];
    const int*   aidx     = (const int*)d_in[4];
    const int*   pidx     = (const int*)d_in[5];
    const int*   nidx     = (const int*)d_in[6];

    lr_fused<<<BLOCKS, 128>>>(anchor, positive, negative, tree,
                              aidx, pidx, nidx, (float*)d_out);
}

// round 12
// speedup vs baseline: 1.0057x; 1.0057x over previous
#include <cuda_runtime.h>

constexpr int B_ = 8192;
constexpr int K_ = 32;
constexpr int D_ = 129;
constexpr int V_ = 2048;
constexpr int KTOP = 10;
constexpr float WEIGHT_ = 0.15f;

// scratch: per-row distances (33 each) + partial sums + completion counter
__device__ float g_d[B_ * 33];
constexpr int BLOCKS2 = B_ / 8;          // phase-2 grid (8 warps/block)
__device__ float g_part[BLOCKS2];
__device__ int   g_count = 0;

__device__ __forceinline__ float warp_sum(float v) {
#pragma unroll
    for (int o = 16; o; o >>= 1) v += __shfl_xor_sync(0xffffffffu, v, o);
    return v;
}
__device__ __forceinline__ float warp_max(float v) {
#pragma unroll
    for (int o = 16; o; o >>= 1) v = fmaxf(v, __shfl_xor_sync(0xffffffffu, v, o));
    return v;
}
__device__ __forceinline__ float acoshd(float x) {
    x = fmaxf(x, 1.0f + 1e-7f);
    return __logf(x + sqrtf(fmaf(x, x, -1.0f)));
}
__device__ __forceinline__ float inv_log2(float n) {
    return __fdividef(1.0f, __log2f(n));
}
__device__ __forceinline__ float pair_term(float ri, float ci, float di,
                                           float rj, float cj, float dj,
                                           float inv_idcg) {
    float drel  = ri - rj;
    float delta = fabsf(drel * (ci - cj)) * inv_idcg;
    float dd    = dj - di;
    float s     = (drel > 0.0f) ? 1.0f : -1.0f;
    float x     = s * dd;
    float sig   = __fdividef(1.0f, 1.0f + __expf(-x));
    return s * delta * sig * (-dd);
}

// 8-item tile: fold 32->8 lanes, transpose-reduce; returns total of item
// (lane & 7), replicated across the four octets. (verified exact in R5/R11)
__device__ __forceinline__ float tile_reduce8(float q[8], int lane) {
#pragma unroll
    for (int k = 0; k < 8; k++) {
        q[k] += __shfl_xor_sync(0xffffffffu, q[k], 16);
        q[k] += __shfl_xor_sync(0xffffffffu, q[k], 8);
    }
    const int ll = lane & 7;
#pragma unroll
    for (int m = 4; m >= 1; m >>= 1) {
        const bool up = (ll & m) != 0;
#pragma unroll
        for (int t = 0; t < m; t++) {
            float send = up ? q[t] : q[t + m];
            float recv = __shfl_xor_sync(0xffffffffu, send, m);
            q[t] = (up ? q[t + m] : q[t]) + recv;
        }
    }
    return q[0];
}

// ===================== phase 1: pure streaming distances =====================
// warp <-> (row b, group g): items 8g..8g+7; group 3 additionally does item 32.
__global__ void __launch_bounds__(256) lr_dist(
    const float* __restrict__ anchor,
    const float* __restrict__ positive,
    const float* __restrict__ negative)
{
    const int wid  = (blockIdx.x * 256 + threadIdx.x) >> 5;
    const int lane = threadIdx.x & 31;
    const int b    = wid >> 2;
    const int g    = wid & 3;

    const float* __restrict__ arow = anchor   + (size_t)b * D_;
    const float* __restrict__ pb   = positive + (size_t)b * D_;
    const float* __restrict__ nb   = negative + (size_t)b * K_ * D_;

    // anchor regs, sign-flipped for c>=1: sum(ah_c * v_c) = -lorentz_inner
    const float ah0 = (lane == 0) ? arow[0] : -arow[lane];
    const float ah1 = -arow[lane + 32];
    const float ah2 = -arow[lane + 64];
    const float ah3 = -arow[lane + 96];
    const float a128n = -arow[128];

    // burst: 8 item partials (+ item 32 for g==3)
    float q[8];
#pragma unroll
    for (int k = 0; k < 8; k++) {
        const int t = 8 * g + k;
        const float* v = (t == 0) ? pb : (nb + (t - 1) * D_);
        q[k] = fmaf(ah0, __ldcs(v + lane), fmaf(ah1, __ldcs(v + lane + 32),
               fmaf(ah2, __ldcs(v + lane + 64), ah3 * __ldcs(v + lane + 96))));
    }
    float p32 = 0.0f, e32 = 0.0f;
    if (g == 3) {
        const float* v = nb + 31 * D_;
        p32 = fmaf(ah0, __ldcs(v + lane), fmaf(ah1, __ldcs(v + lane + 32),
              fmaf(ah2, __ldcs(v + lane + 64), ah3 * __ldcs(v + lane + 96))));
        e32 = __ldcs(v + 128);
    }
    // element-128 tail for item (8g + lane&7), same on every octet (L1 hits)
    const int tl = 8 * g + (lane & 7);
    const float e128 = __ldcs(((tl == 0) ? pb : (nb + (tl - 1) * D_)) + 128);

    const float dsum = tile_reduce8(q, lane) + a128n * e128;
    const float dme  = acoshd(dsum);
    if (lane < 8) g_d[b * 33 + tl] = dme;

    if (g == 3) {
        const float s32 = warp_sum(p32) + a128n * e32;
        if (lane == 0) g_d[b * 33 + 32] = acoshd(s32);
    }
}

// ===================== phase 2: epilogue + global mean =====================
__global__ void __launch_bounds__(256) lr_epi(
    const float* __restrict__ tree,
    const int*   __restrict__ aidx,
    const int*   __restrict__ pidx,
    const int*   __restrict__ nidx,
    float*       __restrict__ out)
{
    __shared__ float s_warp[8];
    __shared__ float s_fin[256];
    __shared__ bool  s_last;

    const int w    = threadIdx.x >> 5;
    const int lane = threadIdx.x & 31;
    const int b    = blockIdx.x * 8 + w;

    // distances from scratch (hot in L2)
    const float dme = g_d[b * 33 + lane];
    const float d32 = g_d[b * 33 + 32];

    // tree gather
    const int ai    = __ldg(aidx + b);
    const int colme = (lane == 0) ? __ldg(pidx + b) : __ldg(nidx + b * K_ + lane - 1);
    const int col32 = __ldg(nidx + b * K_ + 31);
    const float* __restrict__ trow = tree + (size_t)ai * V_;
    const float tme = __ldg(trow + colme);
    const float t32 = __ldg(trow + col32);

    const float maxt   = fmaxf(warp_max(tme), t32);
    const float inv_mt = __fdividef(1.0f, maxt + 1e-6f);
    const float relme  = (maxt - tme + 1e-6f) * inv_mt;
    const float rel32  = (maxt - t32 + 1e-6f) * inv_mt;

    // stable ranks via lane rotation
    int rank = 1, rr = 0;
#pragma unroll
    for (int o = 1; o < 32; o++) {
        const int j = (lane + o) & 31;
        const float dj = __shfl_sync(0xffffffffu, dme,   j);
        const float rj = __shfl_sync(0xffffffffu, relme, j);
        rank += (dj < dme)   || (dj == dme   && j < lane);
        rr   += (rj > relme) || (rj == relme && j < lane);
    }
    rank += (d32 < dme);
    rr   += (rel32 > relme);

    const int rank32 = 1 + (int)__reduce_add_sync(0xffffffffu, (unsigned)(dme <= d32));
    const int rr32   =     (int)__reduce_add_sync(0xffffffffu, (unsigned)(relme >= rel32));

    const float cme = (rank   <= KTOP) ? inv_log2((float)(rank   + 1)) : 0.0f;
    const float c32 = (rank32 <= KTOP) ? inv_log2((float)(rank32 + 1)) : 0.0f;

    float ic = (rr < KTOP) ? relme * inv_log2((float)(rr + 2)) : 0.0f;
    if (lane == 0 && rr32 < KTOP) ic += rel32 * inv_log2((float)(rr32 + 2));
    const float idcg = warp_sum(ic);
    const float inv_idcg = (idcg > 0.0f) ? __fdividef(1.0f, idcg) : 0.0f;

    // pairwise lambda: rotation covers C(32,2); o=16 double-counted
    float acc = 0.0f;
#pragma unroll
    for (int o = 1; o <= 16; o++) {
        const int j = (lane + o) & 31;
        const float rj = __shfl_sync(0xffffffffu, relme, j);
        const float cj = __shfl_sync(0xffffffffu, cme,   j);
        const float dj = __shfl_sync(0xffffffffu, dme,   j);
        const float t  = pair_term(relme, cme, dme, rj, cj, dj, inv_idcg);
        acc += (o == 16) ? 0.5f * t : t;
    }
    acc += pair_term(relme, cme, dme, rel32, c32, d32, inv_idcg);

    acc = warp_sum(acc);
    if (lane == 0) s_warp[w] = acc;
    __syncthreads();

    if (threadIdx.x == 0) {
        float bsum = 0.0f;
#pragma unroll
        for (int i = 0; i < 8; i++) bsum += s_warp[i];
        g_part[blockIdx.x] = bsum;
        __threadfence();
        const int prev = atomicAdd(&g_count, 1);
        s_last = (prev == BLOCKS2 - 1);
    }
    __syncthreads();

    if (s_last) {
        __threadfence();
        float v = 0.0f;
        for (int i = threadIdx.x; i < BLOCKS2; i += 256) v += g_part[i];
        s_fin[threadIdx.x] = v;
        __syncthreads();
#pragma unroll
        for (int o = 128; o; o >>= 1) {
            if (threadIdx.x < o) s_fin[threadIdx.x] += s_fin[threadIdx.x + o];
            __syncthreads();
        }
        if (threadIdx.x == 0) {
            out[0] = WEIGHT_ * s_fin[0] / (float)B_;
            g_count = 0;
        }
    }
}

extern "C" void kernel_launch(void* const* d_in, const int* in_sizes, int n_in,
                              void* d_out, int out_size)
{
    const float* anchor   = (const float*)d_in[0];
    const float* positive = (const float*)d_in[1];
    const float* negative = (const float*)d_in[2];
    const float* tree     = (const float*)d_in[3];
    const int*   aidx     = (const int*)d_in[4];
    const int*   pidx     = (const int*)d_in[5];
    const int*   nidx     = (const int*)d_in[6];

    lr_dist<<<B_ * 4 / 8, 256>>>(anchor, positive, negative);
    lr_epi<<<BLOCKS2, 256>>>(tree, aidx, pidx, nidx, (float*)d_out);
}